// round 4
// baseline (speedup 1.0000x reference)
#include <cuda_runtime.h>
#include <math.h>

// ---------------------------------------------------------------------------
// Categorical 2D semantic map: 16 frames, trilinear splat -> round -> z-sum.
//
//   1) scatter_kernel: per (frame, ds-pixel) computes 8 trilinear corners.
//        - c0 occupancy: scalar atomicAdd into g_c0[f][z][x][y]
//        - sem channels: float4 atomicAdd (4 per corner) into
//          g_sem[f][zr][x][y][c] (c contiguous, 16B-aligned)
//        - touch bitmask: atomicOr of z-bits into g_mask[f][w][x][y]
//   2) reduce_kernel: per (f,x,y) column, iterates ONLY set mask bits,
//      sums rintf(voxel), zeroes consumed cells + mask (scratch stays clean
//      across graph replays), writes all 18 output channels.
// ---------------------------------------------------------------------------

#define H2 120          // 480 / 4
#define W2 160          // 640 / 4
#define VR 100          // VISION_RANGE
#define ZL 80           // Z_LEVELS
#define ZAG_LO 8        // MIN_MAPPED_H
#define ZAG_HI 25       // MAX_MAPPED_H
#define ZAG_N  17
#define NSEM 16
#define NFRAMES 16
#define CH_ELEMS (480 * 640)
#define FRAME_ELEMS (20 * CH_ELEMS)
#define MAPC (VR * VR)

// Zero-initialized at load; reduce_kernel restores zeros each call.
__device__ float g_c0[NFRAMES * ZL * MAPC];                        // [f][z][x][y]
__device__ float4 g_sem[(size_t)NFRAMES * ZAG_N * MAPC * 4];       // [f][zr][x][y][c/4]
__device__ unsigned g_mask[NFRAMES * 3 * MAPC];                    // [f][word][x][y]

__global__ void __launch_bounds__(W2) scatter_kernel(const float* __restrict__ obs,
                                                     const float f_pix) {
    const int j = threadIdx.x;   // ds col
    const int i = blockIdx.x;    // ds row
    const int f = blockIdx.y;    // frame

    const float* frame = obs + (size_t)f * FRAME_ELEMS;
    const float Yd = __ldg(frame + 3 * CH_ELEMS + (4 * i) * 640 + 4 * j);
    if (!(Yd > 20.0f && Yd < 500.0f)) return;

    // Exact float op sequence of the reference.
    const float X  = ((float)(4 * j) - 319.5f) * Yd / f_pix;
    const float Z  = (239.5f - (float)(4 * i)) * Yd / f_pix;
    const float xm = X + 250.0f;
    const float zm = Z + 88.0f;
    const float xn = (xm / 5.0f - 50.0f) / 100.0f * 2.0f;
    const float yn = (Yd / 5.0f - 50.0f) / 100.0f * 2.0f;
    const float zn = (zm / 5.0f - 32.0f) / 80.0f * 2.0f;
    const float posx = xn * 50.0f + 50.0f;
    const float posy = yn * 50.0f + 50.0f;
    const float posz = zn * 40.0f + 40.0f;

    const float bxf = floorf(posx), byf = floorf(posy), bzf = floorf(posz);
    float wx[2], wy[2], wz[2];
#pragma unroll
    for (int t = 0; t < 2; t++) {
        float p;
        p = bxf + (float)t; wx[t] = (p > 0.0f && p < (float)VR) ? (1.0f - fabsf(posx - p)) : 0.0f;
        p = byf + (float)t; wy[t] = (p > 0.0f && p < (float)VR) ? (1.0f - fabsf(posy - p)) : 0.0f;
        p = bzf + (float)t; wz[t] = (p > 0.0f && p < (float)ZL) ? (1.0f - fabsf(posz - p)) : 0.0f;
    }
    if ((wx[0] == 0.0f && wx[1] == 0.0f) ||
        (wy[0] == 0.0f && wy[1] == 0.0f) ||
        (wz[0] == 0.0f && wz[1] == 0.0f)) return;

    const int xb = (int)bxf, yb = (int)byf, zb = (int)bzf;

    // Bitmask words for the touched z levels (no runtime-indexed local array).
    unsigned m0 = 0, m1 = 0, m2 = 0;
    if (wz[0] != 0.0f) {
        const int z = zb;
        if (z < 32) m0 |= 1u << z; else if (z < 64) m1 |= 1u << (z - 32); else m2 |= 1u << (z - 64);
    }
    if (wz[1] != 0.0f) {
        const int z = zb + 1;
        if (z < 32) m0 |= 1u << z; else if (z < 64) m1 |= 1u << (z - 32); else m2 |= 1u << (z - 64);
    }

    float* c0f = g_c0 + f * (ZL * MAPC);
    unsigned* mb = g_mask + f * (3 * MAPC);

#pragma unroll
    for (int tx = 0; tx < 2; tx++) {
        if (wx[tx] == 0.0f) continue;
#pragma unroll
        for (int ty = 0; ty < 2; ty++) {
            const float wq = wx[tx] * wy[ty];
            if (wq <= 0.0f) continue;
            const int off = (xb + tx) * VR + (yb + ty);
            if (m0) atomicOr(mb + off, m0);
            if (m1) atomicOr(mb + MAPC + off, m1);
            if (m2) atomicOr(mb + 2 * MAPC + off, m2);
            if (wz[0] != 0.0f) atomicAdd(c0f + zb * MAPC + off, wq * wz[0]);
            if (wz[1] != 0.0f) atomicAdd(c0f + (zb + 1) * MAPC + off, wq * wz[1]);
        }
    }

    // Sem channels matter only for z in [8,25): gate the 1KB pooled load.
    const bool semz0 = (wz[0] != 0.0f) && (zb >= ZAG_LO) && (zb < ZAG_HI);
    const bool semz1 = (wz[1] != 0.0f) && (zb + 1 >= ZAG_LO) && (zb + 1 < ZAG_HI);
    if (!(semz0 || semz1)) return;

    // 4x4 average pool of 16 semantic channels at this pixel.
    float sem[NSEM];
    const float* sbase = frame + 4 * CH_ELEMS + (4 * i) * 640 + 4 * j;
#pragma unroll
    for (int c = 0; c < NSEM; c++) {
        const float* cp = sbase + c * CH_ELEMS;
        float s = 0.0f;
#pragma unroll
        for (int r = 0; r < 4; r++) {
            float4 v = *reinterpret_cast<const float4*>(cp + r * 640);
            s += v.x + v.y + v.z + v.w;
        }
        sem[c] = s * 0.0625f;
    }

    float4* semf = g_sem + (size_t)f * (ZAG_N * MAPC) * 4;
#pragma unroll
    for (int tz = 0; tz < 2; tz++) {
        if (!(tz == 0 ? semz0 : semz1)) continue;
        const int zr = zb + tz - ZAG_LO;
#pragma unroll
        for (int tx = 0; tx < 2; tx++) {
            if (wx[tx] == 0.0f) continue;
#pragma unroll
            for (int ty = 0; ty < 2; ty++) {
                const float w = (wx[tx] * wy[ty]) * wz[tz];
                if (w <= 0.0f) continue;
                float4* cell = semf + ((size_t)(zr * VR + (xb + tx)) * VR + (yb + ty)) * 4;
                atomicAdd(cell + 0, make_float4(sem[0]  * w, sem[1]  * w, sem[2]  * w, sem[3]  * w));
                atomicAdd(cell + 1, make_float4(sem[4]  * w, sem[5]  * w, sem[6]  * w, sem[7]  * w));
                atomicAdd(cell + 2, make_float4(sem[8]  * w, sem[9]  * w, sem[10] * w, sem[11] * w));
                atomicAdd(cell + 3, make_float4(sem[12] * w, sem[13] * w, sem[14] * w, sem[15] * w));
            }
        }
    }
}

// One block per (f, x); thread = y column. Iterates only set mask bits,
// zeroes every cell and mask word it consumes.
__global__ void __launch_bounds__(VR) reduce_kernel(float* __restrict__ out) {
    const int y = threadIdx.x;
    const int x = blockIdx.x;
    const int f = blockIdx.y;

    unsigned* mb = g_mask + f * (3 * MAPC) + x * VR + y;
    const unsigned m0 = mb[0];
    const unsigned m1 = mb[MAPC];
    const unsigned m2 = mb[2 * MAPC];

    float* c0col = g_c0 + (size_t)f * (ZL * MAPC) + x * VR + y;
    float s_all = 0.0f, s_ag = 0.0f;

    unsigned mm = m0;
    while (mm) {
        const int z = __ffs(mm) - 1; mm &= mm - 1;
        const float v = c0col[z * MAPC];
        c0col[z * MAPC] = 0.0f;
        const float r = rintf(v);
        s_all += r;
        if (z >= ZAG_LO && z < ZAG_HI) s_ag += r;
    }
    mm = m1;
    while (mm) {
        const int z = 32 + __ffs(mm) - 1; mm &= mm - 1;
        const float v = c0col[z * MAPC];
        c0col[z * MAPC] = 0.0f;
        s_all += rintf(v);
    }
    mm = m2;
    while (mm) {
        const int z = 64 + __ffs(mm) - 1; mm &= mm - 1;
        const float v = c0col[z * MAPC];
        c0col[z * MAPC] = 0.0f;
        s_all += rintf(v);
    }

    // Sem: only bits 8..24 of word 0.
    float acc[NSEM];
#pragma unroll
    for (int c = 0; c < NSEM; c++) acc[c] = 0.0f;

    float4* semcol = g_sem + ((size_t)f * (ZAG_N * MAPC) + x * VR + y) * 4;
    unsigned sm = m0 & 0x01FFFF00u;   // bits 8..24
    while (sm) {
        const int z = __ffs(sm) - 1; sm &= sm - 1;
        float4* cell = semcol + (size_t)(z - ZAG_LO) * MAPC * 4;
#pragma unroll
        for (int q = 0; q < 4; q++) {
            const float4 v = cell[q];
            cell[q] = make_float4(0.0f, 0.0f, 0.0f, 0.0f);
            acc[4 * q + 0] += rintf(v.x);
            acc[4 * q + 1] += rintf(v.y);
            acc[4 * q + 2] += rintf(v.z);
            acc[4 * q + 3] += rintf(v.w);
        }
    }

    // Restore mask for the next graph replay (write only if dirty).
    if (m0) mb[0] = 0u;
    if (m1) mb[MAPC] = 0u;
    if (m2) mb[2 * MAPC] = 0u;

    float* o = out + (size_t)f * 18 * MAPC + x * VR + y;
    o[0]    = fminf(fmaxf(s_ag,  0.0f), 1.0f);   // fp_map  (/1.0)
    o[MAPC] = fminf(fmaxf(s_all, 0.0f), 1.0f);   // fp_exp  (/1.0)
#pragma unroll
    for (int c = 0; c < NSEM; c++)
        o[(2 + c) * MAPC] = fminf(fmaxf(acc[c] / 5.0f, 0.0f), 1.0f);   // sem (/5.0)
}

extern "C" void kernel_launch(void* const* d_in, const int* in_sizes, int n_in,
                              void* d_out, int out_size) {
    const float* obs = (const float*)d_in[0];
    float* out = (float*)d_out;
    (void)in_sizes; (void)n_in; (void)out_size;

    // F_PIX computed in double (as numpy does), then narrowed to float32.
    const float f_pix = (float)(320.0 / tan(39.5 * 3.14159265358979323846 / 180.0));

    scatter_kernel<<<dim3(H2, NFRAMES), W2>>>(obs, f_pix);
    reduce_kernel<<<dim3(VR, NFRAMES), VR>>>(out);
}

// round 5
// speedup vs baseline: 3.8274x; 3.8274x over previous
#include <cuda_runtime.h>
#include <math.h>

// ---------------------------------------------------------------------------
// Categorical 2D semantic map: 16 frames, trilinear splat -> round -> z-sum.
//
//   1) scatter_kernel: per (frame, ds-pixel) computes 8 trilinear corners.
//        - c0 occupancy: scalar atomicAdd into g_c0[f][z][col]
//        - sem channels: float4 atomicAdd (4 per corner) into
//          g_sem[f][zr][col][c] (c contiguous, 16B-aligned)
//   2) reduce_kernel: dense, fully-coalesced sweep. One thread per output
//      column (f, x*100+y); sums rintf(voxel) over z for c0 (80 levels) and
//      the 16 sem channels (17 levels), zeroes every nonzero cell it reads
//      (scratch stays clean across graph replays -> no memset pass), writes
//      all 18 output channels.
// ---------------------------------------------------------------------------

#define H2 120          // 480 / 4
#define W2 160          // 640 / 4
#define VR 100          // VISION_RANGE
#define ZL 80           // Z_LEVELS
#define ZAG_LO 8        // MIN_MAPPED_H
#define ZAG_HI 25       // MAX_MAPPED_H
#define ZAG_N  17
#define NSEM 16
#define NFRAMES 16
#define CH_ELEMS (480 * 640)
#define FRAME_ELEMS (20 * CH_ELEMS)
#define MAPC (VR * VR)

// Zero-initialized at load; reduce_kernel restores zeros each call.
__device__ float g_c0[NFRAMES * ZL * MAPC];                        // [f][z][col]
__device__ float4 g_sem[(size_t)NFRAMES * ZAG_N * MAPC * 4];       // [f][zr][col][c/4]

__global__ void __launch_bounds__(W2) scatter_kernel(const float* __restrict__ obs,
                                                     const float f_pix) {
    const int j = threadIdx.x;   // ds col
    const int i = blockIdx.x;    // ds row
    const int f = blockIdx.y;    // frame

    const float* frame = obs + (size_t)f * FRAME_ELEMS;
    const float Yd = __ldg(frame + 3 * CH_ELEMS + (4 * i) * 640 + 4 * j);
    if (!(Yd > 20.0f && Yd < 500.0f)) return;

    // Exact float op sequence of the reference.
    const float X  = ((float)(4 * j) - 319.5f) * Yd / f_pix;
    const float Z  = (239.5f - (float)(4 * i)) * Yd / f_pix;
    const float xm = X + 250.0f;
    const float zm = Z + 88.0f;
    const float xn = (xm / 5.0f - 50.0f) / 100.0f * 2.0f;
    const float yn = (Yd / 5.0f - 50.0f) / 100.0f * 2.0f;
    const float zn = (zm / 5.0f - 32.0f) / 80.0f * 2.0f;
    const float posx = xn * 50.0f + 50.0f;
    const float posy = yn * 50.0f + 50.0f;
    const float posz = zn * 40.0f + 40.0f;

    const float bxf = floorf(posx), byf = floorf(posy), bzf = floorf(posz);
    float wx[2], wy[2], wz[2];
#pragma unroll
    for (int t = 0; t < 2; t++) {
        float p;
        p = bxf + (float)t; wx[t] = (p > 0.0f && p < (float)VR) ? (1.0f - fabsf(posx - p)) : 0.0f;
        p = byf + (float)t; wy[t] = (p > 0.0f && p < (float)VR) ? (1.0f - fabsf(posy - p)) : 0.0f;
        p = bzf + (float)t; wz[t] = (p > 0.0f && p < (float)ZL) ? (1.0f - fabsf(posz - p)) : 0.0f;
    }
    if ((wx[0] == 0.0f && wx[1] == 0.0f) ||
        (wy[0] == 0.0f && wy[1] == 0.0f) ||
        (wz[0] == 0.0f && wz[1] == 0.0f)) return;

    const int xb = (int)bxf, yb = (int)byf, zb = (int)bzf;

    // --- channel 0 (occupancy): all z levels ---
    float* c0f = g_c0 + f * (ZL * MAPC);
#pragma unroll
    for (int tx = 0; tx < 2; tx++) {
        if (wx[tx] == 0.0f) continue;
#pragma unroll
        for (int ty = 0; ty < 2; ty++) {
            const float wq = wx[tx] * wy[ty];
            if (wq <= 0.0f) continue;
            const int off = (xb + tx) * VR + (yb + ty);
            if (wz[0] != 0.0f) atomicAdd(c0f + zb * MAPC + off, wq * wz[0]);
            if (wz[1] != 0.0f) atomicAdd(c0f + (zb + 1) * MAPC + off, wq * wz[1]);
        }
    }

    // Sem channels matter only for z in [8,25): gate the 1KB pooled load.
    const bool semz0 = (wz[0] != 0.0f) && (zb >= ZAG_LO) && (zb < ZAG_HI);
    const bool semz1 = (wz[1] != 0.0f) && (zb + 1 >= ZAG_LO) && (zb + 1 < ZAG_HI);
    if (!(semz0 || semz1)) return;

    // 4x4 average pool of 16 semantic channels at this pixel.
    float sem[NSEM];
    const float* sbase = frame + 4 * CH_ELEMS + (4 * i) * 640 + 4 * j;
#pragma unroll
    for (int c = 0; c < NSEM; c++) {
        const float* cp = sbase + c * CH_ELEMS;
        float s = 0.0f;
#pragma unroll
        for (int r = 0; r < 4; r++) {
            float4 v = *reinterpret_cast<const float4*>(cp + r * 640);
            s += v.x + v.y + v.z + v.w;
        }
        sem[c] = s * 0.0625f;
    }

    float4* semf = g_sem + (size_t)f * (ZAG_N * MAPC) * 4;
#pragma unroll
    for (int tz = 0; tz < 2; tz++) {
        if (!(tz == 0 ? semz0 : semz1)) continue;
        const int zr = zb + tz - ZAG_LO;
#pragma unroll
        for (int tx = 0; tx < 2; tx++) {
            if (wx[tx] == 0.0f) continue;
#pragma unroll
            for (int ty = 0; ty < 2; ty++) {
                const float w = (wx[tx] * wy[ty]) * wz[tz];
                if (w <= 0.0f) continue;
                float4* cell = semf + ((size_t)(zr * VR + (xb + tx)) * VR + (yb + ty)) * 4;
                atomicAdd(cell + 0, make_float4(sem[0]  * w, sem[1]  * w, sem[2]  * w, sem[3]  * w));
                atomicAdd(cell + 1, make_float4(sem[4]  * w, sem[5]  * w, sem[6]  * w, sem[7]  * w));
                atomicAdd(cell + 2, make_float4(sem[8]  * w, sem[9]  * w, sem[10] * w, sem[11] * w));
                atomicAdd(cell + 3, make_float4(sem[12] * w, sem[13] * w, sem[14] * w, sem[15] * w));
            }
        }
    }
}

// Dense coalesced sweep. grid = (ceil(10000/256)=40, 16 frames), block = 256.
// Thread -> one output column; all loads full-width coalesced, unrolled for MLP.
__global__ void __launch_bounds__(256) reduce_kernel(float* __restrict__ out) {
    const int col = blockIdx.x * 256 + threadIdx.x;
    const int f = blockIdx.y;
    if (col >= MAPC) return;

    // --- c0: 80 z-levels, stride MAPC ---
    float* c0col = g_c0 + (size_t)f * (ZL * MAPC) + col;
    float s_all = 0.0f, s_ag = 0.0f;
#pragma unroll 16
    for (int z = 0; z < ZL; z++) {
        const float v = c0col[(size_t)z * MAPC];
        if (v != 0.0f) {
            c0col[(size_t)z * MAPC] = 0.0f;      // restore scratch for next replay
            const float r = rintf(v);            // jnp.round = half-to-even
            s_all += r;
            if (z >= ZAG_LO && z < ZAG_HI) s_ag += r;
        }
    }

    // --- sem: 17 z-levels x 16 channels (4 x float4 per cell, coalesced) ---
    float acc[NSEM];
#pragma unroll
    for (int c = 0; c < NSEM; c++) acc[c] = 0.0f;

    float4* semcol = g_sem + ((size_t)f * (ZAG_N * MAPC) + col) * 4;
#pragma unroll
    for (int zr = 0; zr < ZAG_N; zr++) {
        float4* cell = semcol + (size_t)zr * MAPC * 4;
        const float4 v0 = cell[0];
        const float4 v1 = cell[1];
        const float4 v2 = cell[2];
        const float4 v3 = cell[3];
        // rintf(0) == 0, so accumulate unconditionally; store zeros only if dirty.
        acc[0]  += rintf(v0.x); acc[1]  += rintf(v0.y); acc[2]  += rintf(v0.z); acc[3]  += rintf(v0.w);
        acc[4]  += rintf(v1.x); acc[5]  += rintf(v1.y); acc[6]  += rintf(v1.z); acc[7]  += rintf(v1.w);
        acc[8]  += rintf(v2.x); acc[9]  += rintf(v2.y); acc[10] += rintf(v2.z); acc[11] += rintf(v2.w);
        acc[12] += rintf(v3.x); acc[13] += rintf(v3.y); acc[14] += rintf(v3.z); acc[15] += rintf(v3.w);
        const float4 zf = make_float4(0.0f, 0.0f, 0.0f, 0.0f);
        if (v0.x != 0.0f || v0.y != 0.0f || v0.z != 0.0f || v0.w != 0.0f) cell[0] = zf;
        if (v1.x != 0.0f || v1.y != 0.0f || v1.z != 0.0f || v1.w != 0.0f) cell[1] = zf;
        if (v2.x != 0.0f || v2.y != 0.0f || v2.z != 0.0f || v2.w != 0.0f) cell[2] = zf;
        if (v3.x != 0.0f || v3.y != 0.0f || v3.z != 0.0f || v3.w != 0.0f) cell[3] = zf;
    }

    float* o = out + (size_t)f * 18 * MAPC + col;
    o[0]    = fminf(fmaxf(s_ag,  0.0f), 1.0f);   // fp_map  (/1.0)
    o[MAPC] = fminf(fmaxf(s_all, 0.0f), 1.0f);   // fp_exp  (/1.0)
#pragma unroll
    for (int c = 0; c < NSEM; c++)
        o[(2 + c) * MAPC] = fminf(fmaxf(acc[c] / 5.0f, 0.0f), 1.0f);   // sem (/5.0)
}

extern "C" void kernel_launch(void* const* d_in, const int* in_sizes, int n_in,
                              void* d_out, int out_size) {
    const float* obs = (const float*)d_in[0];
    float* out = (float*)d_out;
    (void)in_sizes; (void)n_in; (void)out_size;

    // F_PIX computed in double (as numpy does), then narrowed to float32.
    const float f_pix = (float)(320.0 / tan(39.5 * 3.14159265358979323846 / 180.0));

    scatter_kernel<<<dim3(H2, NFRAMES), W2>>>(obs, f_pix);
    reduce_kernel<<<dim3((MAPC + 255) / 256, NFRAMES), 256>>>(out);
}

// round 6
// speedup vs baseline: 5.9098x; 1.5441x over previous
#include <cuda_runtime.h>
#include <math.h>

// ---------------------------------------------------------------------------
// Categorical 2D semantic map: 16 frames, trilinear splat -> round -> z-sum.
//
//   1) scatter_kernel: per (frame, ds-pixel) computes 8 trilinear corners.
//        - c0 occupancy: scalar atomicAdd into g_c0[f][z][col]
//        - sem channels: float4 atomicAdd (4 per corner) into
//          g_sem[f][zr][col][c] (c contiguous, 16B-aligned)
//      Input loads use __ldcs (streaming) so they don't evict scratch from L2.
//   2) reduce_kernel: dense, fully-coalesced sweep split into two uniform
//      work classes by block index (no intra-warp divergence):
//        - c0 class: thread per column, 80 coalesced loads -> 2 outputs
//        - sem class: thread per (column, float4-quad), 17 coalesced float4
//          loads -> 4 channel outputs
//      Every nonzero cell read is zeroed (scratch stays clean across graph
//      replays -> no memset pass needed).
// ---------------------------------------------------------------------------

#define H2 120          // 480 / 4
#define W2 160          // 640 / 4
#define VR 100          // VISION_RANGE
#define ZL 80           // Z_LEVELS
#define ZAG_LO 8        // MIN_MAPPED_H
#define ZAG_HI 25       // MAX_MAPPED_H
#define ZAG_N  17
#define NSEM 16
#define NFRAMES 16
#define CH_ELEMS (480 * 640)
#define FRAME_ELEMS (20 * CH_ELEMS)
#define MAPC (VR * VR)

#define C0_BLOCKS  40   // 40*256 = 10240 >= 10000 columns
#define SEM_BLOCKS 157  // 157*256 = 40192 >= 40000 (column, quad) items

// Zero-initialized at load; reduce_kernel restores zeros each call.
__device__ float g_c0[NFRAMES * ZL * MAPC];                        // [f][z][col]
__device__ float4 g_sem[(size_t)NFRAMES * ZAG_N * MAPC * 4];       // [f][zr][col][c/4]

__global__ void __launch_bounds__(W2) scatter_kernel(const float* __restrict__ obs,
                                                     const float f_pix) {
    const int j = threadIdx.x;   // ds col
    const int i = blockIdx.x;    // ds row
    const int f = blockIdx.y;    // frame

    const float* frame = obs + (size_t)f * FRAME_ELEMS;
    const float Yd = __ldcs(frame + 3 * CH_ELEMS + (4 * i) * 640 + 4 * j);
    if (!(Yd > 20.0f && Yd < 500.0f)) return;

    // Exact float op sequence of the reference.
    const float X  = ((float)(4 * j) - 319.5f) * Yd / f_pix;
    const float Z  = (239.5f - (float)(4 * i)) * Yd / f_pix;
    const float xm = X + 250.0f;
    const float zm = Z + 88.0f;
    const float xn = (xm / 5.0f - 50.0f) / 100.0f * 2.0f;
    const float yn = (Yd / 5.0f - 50.0f) / 100.0f * 2.0f;
    const float zn = (zm / 5.0f - 32.0f) / 80.0f * 2.0f;
    const float posx = xn * 50.0f + 50.0f;
    const float posy = yn * 50.0f + 50.0f;
    const float posz = zn * 40.0f + 40.0f;

    const float bxf = floorf(posx), byf = floorf(posy), bzf = floorf(posz);
    float wx[2], wy[2], wz[2];
#pragma unroll
    for (int t = 0; t < 2; t++) {
        float p;
        p = bxf + (float)t; wx[t] = (p > 0.0f && p < (float)VR) ? (1.0f - fabsf(posx - p)) : 0.0f;
        p = byf + (float)t; wy[t] = (p > 0.0f && p < (float)VR) ? (1.0f - fabsf(posy - p)) : 0.0f;
        p = bzf + (float)t; wz[t] = (p > 0.0f && p < (float)ZL) ? (1.0f - fabsf(posz - p)) : 0.0f;
    }
    if ((wx[0] == 0.0f && wx[1] == 0.0f) ||
        (wy[0] == 0.0f && wy[1] == 0.0f) ||
        (wz[0] == 0.0f && wz[1] == 0.0f)) return;

    const int xb = (int)bxf, yb = (int)byf, zb = (int)bzf;

    // --- channel 0 (occupancy): all z levels ---
    float* c0f = g_c0 + f * (ZL * MAPC);
#pragma unroll
    for (int tx = 0; tx < 2; tx++) {
        if (wx[tx] == 0.0f) continue;
#pragma unroll
        for (int ty = 0; ty < 2; ty++) {
            const float wq = wx[tx] * wy[ty];
            if (wq <= 0.0f) continue;
            const int off = (xb + tx) * VR + (yb + ty);
            if (wz[0] != 0.0f) atomicAdd(c0f + zb * MAPC + off, wq * wz[0]);
            if (wz[1] != 0.0f) atomicAdd(c0f + (zb + 1) * MAPC + off, wq * wz[1]);
        }
    }

    // Sem channels matter only for z in [8,25): gate the 1KB pooled load.
    const bool semz0 = (wz[0] != 0.0f) && (zb >= ZAG_LO) && (zb < ZAG_HI);
    const bool semz1 = (wz[1] != 0.0f) && (zb + 1 >= ZAG_LO) && (zb + 1 < ZAG_HI);
    if (!(semz0 || semz1)) return;

    // 4x4 average pool of 16 semantic channels at this pixel (streaming loads).
    float sem[NSEM];
    const float* sbase = frame + 4 * CH_ELEMS + (4 * i) * 640 + 4 * j;
#pragma unroll
    for (int c = 0; c < NSEM; c++) {
        const float* cp = sbase + c * CH_ELEMS;
        float s = 0.0f;
#pragma unroll
        for (int r = 0; r < 4; r++) {
            float4 v = __ldcs(reinterpret_cast<const float4*>(cp + r * 640));
            s += v.x + v.y + v.z + v.w;
        }
        sem[c] = s * 0.0625f;
    }

    float4* semf = g_sem + (size_t)f * (ZAG_N * MAPC) * 4;
#pragma unroll
    for (int tz = 0; tz < 2; tz++) {
        if (!(tz == 0 ? semz0 : semz1)) continue;
        const int zr = zb + tz - ZAG_LO;
#pragma unroll
        for (int tx = 0; tx < 2; tx++) {
            if (wx[tx] == 0.0f) continue;
#pragma unroll
            for (int ty = 0; ty < 2; ty++) {
                const float w = (wx[tx] * wy[ty]) * wz[tz];
                if (w <= 0.0f) continue;
                float4* cell = semf + ((size_t)(zr * VR + (xb + tx)) * VR + (yb + ty)) * 4;
                atomicAdd(cell + 0, make_float4(sem[0]  * w, sem[1]  * w, sem[2]  * w, sem[3]  * w));
                atomicAdd(cell + 1, make_float4(sem[4]  * w, sem[5]  * w, sem[6]  * w, sem[7]  * w));
                atomicAdd(cell + 2, make_float4(sem[8]  * w, sem[9]  * w, sem[10] * w, sem[11] * w));
                atomicAdd(cell + 3, make_float4(sem[12] * w, sem[13] * w, sem[14] * w, sem[15] * w));
            }
        }
    }
}

// grid = (C0_BLOCKS + SEM_BLOCKS, NFRAMES), block = 256.
// Block-range partition keeps every warp uniform.
__global__ void __launch_bounds__(256) reduce_kernel(float* __restrict__ out) {
    const int f = blockIdx.y;
    float* o = out + (size_t)f * 18 * MAPC;

    if (blockIdx.x < C0_BLOCKS) {
        // ---- c0 class: one thread per column, 80 z-levels ----
        const int col = blockIdx.x * 256 + threadIdx.x;
        if (col >= MAPC) return;
        float* c0col = g_c0 + (size_t)f * (ZL * MAPC) + col;
        float s_all = 0.0f, s_ag = 0.0f;
#pragma unroll 20
        for (int z = 0; z < ZL; z++) {
            const float v = c0col[(size_t)z * MAPC];
            if (v != 0.0f) {
                c0col[(size_t)z * MAPC] = 0.0f;      // restore scratch for next replay
                const float r = rintf(v);            // jnp.round = half-to-even
                s_all += r;
                if (z >= ZAG_LO && z < ZAG_HI) s_ag += r;
            }
        }
        o[col]        = fminf(fmaxf(s_ag,  0.0f), 1.0f);   // fp_map (/1.0)
        o[MAPC + col] = fminf(fmaxf(s_all, 0.0f), 1.0f);   // fp_exp (/1.0)
    } else {
        // ---- sem class: one thread per (column, float4-quad) ----
        const int item = (blockIdx.x - C0_BLOCKS) * 256 + threadIdx.x;
        if (item >= MAPC * 4) return;
        const int q = item & 3;           // which float4 (channels 4q..4q+3)
        const int col = item >> 2;
        float4* cell = g_sem + ((size_t)f * (ZAG_N * MAPC) + col) * 4 + q;
        float a0 = 0.0f, a1 = 0.0f, a2 = 0.0f, a3 = 0.0f;
        const float4 zf = make_float4(0.0f, 0.0f, 0.0f, 0.0f);
#pragma unroll
        for (int zr = 0; zr < ZAG_N; zr++) {
            const float4 v = cell[(size_t)zr * MAPC * 4];
            a0 += rintf(v.x); a1 += rintf(v.y); a2 += rintf(v.z); a3 += rintf(v.w);
            if (v.x != 0.0f || v.y != 0.0f || v.z != 0.0f || v.w != 0.0f)
                cell[(size_t)zr * MAPC * 4] = zf;    // restore scratch
        }
        const int c = 4 * q;
        o[(2 + c + 0) * MAPC + col] = fminf(fmaxf(a0 / 5.0f, 0.0f), 1.0f);
        o[(2 + c + 1) * MAPC + col] = fminf(fmaxf(a1 / 5.0f, 0.0f), 1.0f);
        o[(2 + c + 2) * MAPC + col] = fminf(fmaxf(a2 / 5.0f, 0.0f), 1.0f);
        o[(2 + c + 3) * MAPC + col] = fminf(fmaxf(a3 / 5.0f, 0.0f), 1.0f);
    }
}

extern "C" void kernel_launch(void* const* d_in, const int* in_sizes, int n_in,
                              void* d_out, int out_size) {
    const float* obs = (const float*)d_in[0];
    float* out = (float*)d_out;
    (void)in_sizes; (void)n_in; (void)out_size;

    // F_PIX computed in double (as numpy does), then narrowed to float32.
    const float f_pix = (float)(320.0 / tan(39.5 * 3.14159265358979323846 / 180.0));

    scatter_kernel<<<dim3(H2, NFRAMES), W2>>>(obs, f_pix);
    reduce_kernel<<<dim3(C0_BLOCKS + SEM_BLOCKS, NFRAMES), 256>>>(out);
}